// round 4
// baseline (speedup 1.0000x reference)
#include <cuda_runtime.h>
#include <math.h>

#define BB 2
#define LL 2048
#define DM 1024
#define NH 16
#define DK 64
#define BH (BB*NH)

// ---------------- scratch ----------------
__device__ float g_Q[(size_t)BB*NH*LL*DK];
__device__ float g_K[(size_t)BB*NH*LL*DK];
__device__ float g_V[(size_t)BB*NH*LL*DK];
__device__ float g_C[(size_t)BB*LL*DM];
__device__ float g_P[(size_t)BB*NH*LL*LL];     // raw logits
__device__ float g_m[(size_t)BB*NH*LL];
__device__ float g_s[(size_t)BB*NH*LL];
__device__ float g_c[(size_t)BB*NH*LL];
__device__ float g_rb[(size_t)BB*LL];

// ---------------- helpers ----------------
__device__ __forceinline__ unsigned f2tf(float f) {
    unsigned u; asm("cvt.rna.tf32.f32 %0, %1;" : "=r"(u) : "f"(f)); return u;
}
__device__ __forceinline__ void mma8(float* c, const unsigned* a, const unsigned* b) {
    asm volatile("mma.sync.aligned.m16n8k8.row.col.f32.tf32.tf32.f32 "
        "{%0,%1,%2,%3}, {%4,%5,%6,%7}, {%8,%9}, {%0,%1,%2,%3};"
        : "+f"(c[0]), "+f"(c[1]), "+f"(c[2]), "+f"(c[3])
        : "r"(a[0]), "r"(a[1]), "r"(a[2]), "r"(a[3]), "r"(b[0]), "r"(b[1]));
}

// ---------------- small precomputes ----------------
__global__ void rb_kernel(const float* __restrict__ delta)
{
    int i = blockIdx.x * 256 + threadIdx.x;
    if (i < BB*LL) g_rb[i] = logf(delta[i] + 1e-6f);
}
__global__ void c_kernel()
{
    int i = blockIdx.x * 256 + threadIdx.x;
    if (i < BH*LL) g_c[i] = g_m[i] + __logf(g_s[i]);
}

// =====================================================================
// QKV projection: 128x128 block, 8 warps (2x4) of 64x32, 3xTF32
// =====================================================================
__global__ __launch_bounds__(256) void qkv_gemm(
    const float* __restrict__ x, const float* __restrict__ delta,
    const float* __restrict__ Wq, const float* __restrict__ bq,
    const float* __restrict__ Wk, const float* __restrict__ bk,
    const float* __restrict__ Wv, const float* __restrict__ bv)
{
    extern __shared__ unsigned sm_u[];
    unsigned* Ah = sm_u;            // 4096 u
    unsigned* Al = Ah + 4096;
    unsigned* Bh = Al + 4096;
    unsigned* Bl = Bh + 4096;

    const int which = blockIdx.z;
    const float* W    = (which == 0) ? Wq : (which == 1) ? Wk : Wv;
    const float* bias = (which == 0) ? bq : (which == 1) ? bk : bv;
    float* O          = (which == 0) ? g_Q : (which == 1) ? g_K : g_V;

    const int m0 = blockIdx.y * 128, n0 = blockIdx.x * 128;
    const int tid = threadIdx.x, lane = tid & 31, warp = tid >> 5;
    const int wm = warp >> 2, wn = warp & 3;
    const int g = lane >> 2, t = lane & 3;

    const int am = tid >> 1;
    const float ascale = (which == 2) ? delta[m0 + am] : 1.0f;
    const int bkr = tid >> 3;

    float c[4][4][4] = {};

    for (int kk = 0; kk < DM; kk += 32) {
        if (kk) __syncthreads();
        {   // A tile 128x32 -> hi/lo frag layout
            const float* ap = &x[(size_t)(m0 + am) * DM + kk];
            int mf = am >> 4, gg = am & 7, hm = (am >> 3) & 1;
            #pragma unroll
            for (int it = 0; it < 4; it++) {
                int k0 = (tid & 1) * 16 + it * 4;
                float4 v = *(const float4*)(ap + k0);
                v.x *= ascale; v.y *= ascale; v.z *= ascale; v.w *= ascale;
                int k8 = k0 >> 3, hk = (k0 >> 2) & 1, r = hm + 2 * hk;
                int base = ((mf * 4 + k8) * 32 + gg * 4) * 4 + r;
                unsigned h0 = f2tf(v.x), h1 = f2tf(v.y), h2 = f2tf(v.z), h3 = f2tf(v.w);
                Ah[base] = h0; Ah[base+4] = h1; Ah[base+8] = h2; Ah[base+12] = h3;
                Al[base]    = f2tf(v.x - __uint_as_float(h0));
                Al[base+4]  = f2tf(v.y - __uint_as_float(h1));
                Al[base+8]  = f2tf(v.z - __uint_as_float(h2));
                Al[base+12] = f2tf(v.w - __uint_as_float(h3));
            }
        }
        {   // B tile 32x128 -> hi/lo frag layout
            const float* bp = &W[(size_t)(kk + bkr) * DM + n0];
            int tig = bkr & 3, k8 = bkr >> 3, r = (bkr >> 2) & 1;
            #pragma unroll
            for (int it = 0; it < 4; it++) {
                int ne = (tid & 7) * 16 + it * 4;
                float4 v = *(const float4*)(bp + ne);
                int nf = ne >> 3, g0 = ne & 7;
                int base = ((nf * 4 + k8) * 32 + g0 * 4 + tig) * 2 + r;
                unsigned h0 = f2tf(v.x), h1 = f2tf(v.y), h2 = f2tf(v.z), h3 = f2tf(v.w);
                Bh[base] = h0; Bh[base+8] = h1; Bh[base+16] = h2; Bh[base+24] = h3;
                Bl[base]    = f2tf(v.x - __uint_as_float(h0));
                Bl[base+8]  = f2tf(v.y - __uint_as_float(h1));
                Bl[base+16] = f2tf(v.z - __uint_as_float(h2));
                Bl[base+24] = f2tf(v.w - __uint_as_float(h3));
            }
        }
        __syncthreads();
        #pragma unroll
        for (int k8 = 0; k8 < 4; k8++) {
            unsigned ah[4][4], al[4][4], bhf[4][2], blf[4][2];
            #pragma unroll
            for (int i = 0; i < 4; i++) {
                int base = (((wm * 4 + i) * 4 + k8) * 32 + lane) * 4;
                *(uint4*)ah[i] = *(const uint4*)&Ah[base];
                *(uint4*)al[i] = *(const uint4*)&Al[base];
            }
            #pragma unroll
            for (int j = 0; j < 4; j++) {
                int base = (((wn * 4 + j) * 4 + k8) * 32 + lane) * 2;
                *(uint2*)bhf[j] = *(const uint2*)&Bh[base];
                *(uint2*)blf[j] = *(const uint2*)&Bl[base];
            }
            #pragma unroll
            for (int i = 0; i < 4; i++)
                #pragma unroll
                for (int j = 0; j < 4; j++) {
                    mma8(c[i][j], ah[i], bhf[j]);
                    mma8(c[i][j], ah[i], blf[j]);
                    mma8(c[i][j], al[i], bhf[j]);
                }
        }
    }

    #pragma unroll
    for (int i = 0; i < 4; i++) {
        #pragma unroll
        for (int j = 0; j < 4; j++) {
            int gn = n0 + wn * 32 + j * 8 + t * 2;
            int h = gn >> 6, d = gn & 63;
            float b0 = bias[gn], b1 = bias[gn + 1];
            int r0 = m0 + wm * 64 + i * 16 + g;
            int bb0 = r0 >> 11, l0 = r0 & (LL - 1);
            *(float2*)&O[(((size_t)(bb0 * NH + h)) * LL + l0) * DK + d] =
                make_float2(c[i][j][0] + b0, c[i][j][1] + b1);
            int r1 = r0 + 8;
            int bb1 = r1 >> 11, l1 = r1 & (LL - 1);
            *(float2*)&O[(((size_t)(bb1 * NH + h)) * LL + l1) * DK + d] =
                make_float2(c[i][j][2] + b0, c[i][j][3] + b1);
        }
    }
}

// =====================================================================
// Scores: per block 128 q x all 2048 k, tf32 MMA, online softmax stats
// =====================================================================
__global__ __launch_bounds__(256) void scores_kernel()
{
    extern __shared__ unsigned sm_u[];
    unsigned* Qs = sm_u;              // 8192 u
    unsigned* Ks = Qs + 8192;         // 8192 u
    float* rbs = (float*)(Ks + 8192); // 128
    float* smM = rbs + 128;           // 512
    float* smS = smM + 512;           // 512

    const int bh = blockIdx.y, b = bh >> 4;
    const int q0 = blockIdx.x * 128;
    const int tid = threadIdx.x, lane = tid & 31, warp = tid >> 5;
    const int wm = warp >> 2, wn = warp & 3;
    const int g = lane >> 2, t = lane & 3;

    {   // Q tile 128x64 -> frag layout (loaded once)
        int m = tid >> 1;
        const float* qp = &g_Q[(((size_t)bh) * LL + q0 + m) * DK];
        int mf = m >> 4, gg = m & 7, hm = (m >> 3) & 1;
        #pragma unroll
        for (int it = 0; it < 8; it++) {
            int k0 = (tid & 1) * 32 + it * 4;
            float4 v = *(const float4*)(qp + k0);
            int k8 = k0 >> 3, hk = (k0 >> 2) & 1, r = hm + 2 * hk;
            int base = ((mf * 8 + k8) * 32 + gg * 4) * 4 + r;
            Qs[base] = f2tf(v.x); Qs[base+4] = f2tf(v.y);
            Qs[base+8] = f2tf(v.z); Qs[base+12] = f2tf(v.w);
        }
    }

    float mr[4][2], sr[4][2];
    #pragma unroll
    for (int i = 0; i < 4; i++) { mr[i][0] = mr[i][1] = -1e30f; sr[i][0] = sr[i][1] = 0.0f; }

    for (int kt = 0; kt < LL / 128; kt++) {
        __syncthreads();
        {   // K tile 128x64 -> B-frag layout
            int n = tid >> 1;
            const float* kp = &g_K[(((size_t)bh) * LL + kt * 128 + n) * DK];
            int nf = n >> 3, gg = n & 7;
            #pragma unroll
            for (int it = 0; it < 8; it++) {
                int k0 = (tid & 1) * 32 + it * 4;
                float4 v = *(const float4*)(kp + k0);
                int k8 = k0 >> 3, r = (k0 >> 2) & 1;
                int base = ((nf * 8 + k8) * 32 + gg * 4) * 2 + r;
                Ks[base] = f2tf(v.x); Ks[base+2] = f2tf(v.y);
                Ks[base+4] = f2tf(v.z); Ks[base+6] = f2tf(v.w);
            }
            if (tid < 128) rbs[tid] = g_rb[(size_t)b * LL + kt * 128 + tid];
        }
        __syncthreads();

        float c[4][4][4] = {};
        #pragma unroll
        for (int k8 = 0; k8 < 8; k8++) {
            unsigned a[4][4], bf[4][2];
            #pragma unroll
            for (int i = 0; i < 4; i++) {
                int base = (((wm * 4 + i) * 8 + k8) * 32 + lane) * 4;
                *(uint4*)a[i] = *(const uint4*)&Qs[base];
            }
            #pragma unroll
            for (int j = 0; j < 4; j++) {
                int base = (((wn * 4 + j) * 8 + k8) * 32 + lane) * 2;
                *(uint2*)bf[j] = *(const uint2*)&Ks[base];
            }
            #pragma unroll
            for (int i = 0; i < 4; i++)
                #pragma unroll
                for (int j = 0; j < 4; j++)
                    mma8(c[i][j], a[i], bf[j]);
        }

        // bias + P store + online stats
        #pragma unroll
        for (int i = 0; i < 4; i++) {
            int row0 = q0 + wm * 64 + i * 16 + g;
            #pragma unroll
            for (int half = 0; half < 2; half++) {
                int row = row0 + half * 8;
                float qrf = (float)row;
                float sv[4][2];
                float vmax = -1e30f;
                #pragma unroll
                for (int j = 0; j < 4; j++) {
                    int lcol = wn * 32 + j * 8 + t * 2;
                    int kg = kt * 128 + lcol;
                    float v0 = c[i][j][half*2+0] * 0.125f - 0.1f * fabsf(qrf - (float)kg)     + rbs[lcol];
                    float v1 = c[i][j][half*2+1] * 0.125f - 0.1f * fabsf(qrf - (float)(kg+1)) + rbs[lcol+1];
                    sv[j][0] = v0; sv[j][1] = v1;
                    vmax = fmaxf(vmax, fmaxf(v0, v1));
                    __stcs((float2*)&g_P[(((size_t)bh) * LL + row) * LL + kg],
                           make_float2(v0, v1));
                }
                vmax = fmaxf(vmax, __shfl_xor_sync(0xffffffffu, vmax, 1));
                vmax = fmaxf(vmax, __shfl_xor_sync(0xffffffffu, vmax, 2));
                float newm = fmaxf(mr[i][half], vmax);
                float se = 0.0f;
                #pragma unroll
                for (int j = 0; j < 4; j++)
                    se += __expf(sv[j][0] - newm) + __expf(sv[j][1] - newm);
                se += __shfl_xor_sync(0xffffffffu, se, 1);
                se += __shfl_xor_sync(0xffffffffu, se, 2);
                sr[i][half] = sr[i][half] * __expf(mr[i][half] - newm) + se;
                mr[i][half] = newm;
            }
        }
    }

    __syncthreads();
    if (t == 0) {
        #pragma unroll
        for (int i = 0; i < 4; i++)
            #pragma unroll
            for (int half = 0; half < 2; half++) {
                int row = wm * 64 + i * 16 + half * 8 + g;
                smM[wn * 128 + row] = mr[i][half];
                smS[wn * 128 + row] = sr[i][half];
            }
    }
    __syncthreads();
    if (tid < 128) {
        float M = smM[tid];
        #pragma unroll
        for (int w = 1; w < 4; w++) M = fmaxf(M, smM[w * 128 + tid]);
        float S = 0.0f;
        #pragma unroll
        for (int w = 0; w < 4; w++) S += smS[w * 128 + tid] * __expf(smM[w * 128 + tid] - M);
        g_m[(size_t)bh * LL + q0 + tid] = M;
        g_s[(size_t)bh * LL + q0 + tid] = S;
    }
}

// =====================================================================
// Context: softmax(P) @ V, tf32 MMA; 128q x 64d, K-chunks of 64 keys
// =====================================================================
__global__ __launch_bounds__(256) void context_kernel()
{
    extern __shared__ unsigned sm_u[];
    unsigned* Ps = sm_u;           // 8192 u
    unsigned* Vs = Ps + 8192;      // 4096 u
    float* mrow = (float*)(Vs + 4096);
    float* irow = mrow + 128;

    const int bh = blockIdx.y, b = bh >> 4, hh = bh & 15;
    const int q0 = blockIdx.x * 128;
    const int tid = threadIdx.x, lane = tid & 31, warp = tid >> 5;
    const int wm = warp >> 1, wn = warp & 1;
    const int g = lane >> 2, t = lane & 3;

    if (tid < 128) {
        size_t r = (size_t)bh * LL + q0 + tid;
        mrow[tid] = g_m[r];
        irow[tid] = 1.0f / g_s[r];
    }
    __syncthreads();

    const int pm = tid >> 1;
    const float pmax = mrow[pm];
    const float* Pbase = &g_P[(((size_t)bh) * LL + q0 + pm) * LL];
    const int vk = tid >> 2;

    float c[2][4][4] = {};

    for (int kc = 0; kc < LL; kc += 64) {
        if (kc) __syncthreads();
        {   // P chunk 128x64: exp + tf32 -> A-frag layout
            int mf = pm >> 4, gg = pm & 7, hm = (pm >> 3) & 1;
            #pragma unroll
            for (int it = 0; it < 8; it++) {
                int k0 = (tid & 1) * 32 + it * 4;
                float4 v = __ldcs((const float4*)(Pbase + kc + k0));
                int k8 = k0 >> 3, hk = (k0 >> 2) & 1, r = hm + 2 * hk;
                int base = ((mf * 8 + k8) * 32 + gg * 4) * 4 + r;
                Ps[base]    = f2tf(__expf(v.x - pmax));
                Ps[base+4]  = f2tf(__expf(v.y - pmax));
                Ps[base+8]  = f2tf(__expf(v.z - pmax));
                Ps[base+12] = f2tf(__expf(v.w - pmax));
            }
        }
        {   // V chunk 64x64 -> B-frag layout
            const float* vp = &g_V[(((size_t)bh) * LL + kc + vk) * DK];
            int tig = vk & 3, k8 = vk >> 3, r = (vk >> 2) & 1;
            #pragma unroll
            for (int it = 0; it < 4; it++) {
                int ne = (tid & 3) * 16 + it * 4;
                float4 v = *(const float4*)(vp + ne);
                int nf = ne >> 3, g0 = ne & 7;
                int base = ((nf * 8 + k8) * 32 + g0 * 4 + tig) * 2 + r;
                Vs[base] = f2tf(v.x); Vs[base+8] = f2tf(v.y);
                Vs[base+16] = f2tf(v.z); Vs[base+24] = f2tf(v.w);
            }
        }
        __syncthreads();
        #pragma unroll
        for (int k8 = 0; k8 < 8; k8++) {
            unsigned a[2][4], bf[4][2];
            #pragma unroll
            for (int i = 0; i < 2; i++) {
                int base = (((wm * 2 + i) * 8 + k8) * 32 + lane) * 4;
                *(uint4*)a[i] = *(const uint4*)&Ps[base];
            }
            #pragma unroll
            for (int j = 0; j < 4; j++) {
                int base = (((wn * 4 + j) * 8 + k8) * 32 + lane) * 2;
                *(uint2*)bf[j] = *(const uint2*)&Vs[base];
            }
            #pragma unroll
            for (int i = 0; i < 2; i++)
                #pragma unroll
                for (int j = 0; j < 4; j++)
                    mma8(c[i][j], a[i], bf[j]);
        }
    }

    #pragma unroll
    for (int i = 0; i < 2; i++) {
        int lq0 = wm * 32 + i * 16 + g;
        #pragma unroll
        for (int j = 0; j < 4; j++) {
            int d = wn * 32 + j * 8 + t * 2;
            {
                float sc = irow[lq0];
                int q = q0 + lq0;
                *(float2*)&g_C[((size_t)(b * LL + q)) * DM + hh * 64 + d] =
                    make_float2(c[i][j][0] * sc, c[i][j][1] * sc);
            }
            {
                float sc = irow[lq0 + 8];
                int q = q0 + lq0 + 8;
                *(float2*)&g_C[((size_t)(b * LL + q)) * DM + hh * 64 + d] =
                    make_float2(c[i][j][2] * sc, c[i][j][3] * sc);
            }
        }
    }
}

// =====================================================================
// Head-mean of attention
// =====================================================================
__global__ void mean_kernel(float* __restrict__ outmean)
{
    size_t idx4 = (size_t)blockIdx.x * 256 + threadIdx.x;
    int k4 = (int)(idx4 & (LL / 4 - 1)) * 4;
    size_t bq = idx4 / (LL / 4);
    int q = (int)(bq & (LL - 1));
    int b = (int)(bq >> 11);
    float ax = 0, ay = 0, az = 0, aw = 0;
    #pragma unroll
    for (int h = 0; h < NH; h++) {
        int bh = b * NH + h;
        float cc = g_c[(size_t)bh * LL + q];
        float4 v = __ldcs((const float4*)&g_P[((size_t)bh * LL + q) * LL + k4]);
        ax += __expf(v.x - cc); ay += __expf(v.y - cc);
        az += __expf(v.z - cc); aw += __expf(v.w - cc);
    }
    const float inv = 1.0f / NH;
    *(float4*)&outmean[bq * LL + k4] = make_float4(ax*inv, ay*inv, az*inv, aw*inv);
}

// =====================================================================
// Output projection: 3xTF32, same structure as qkv
// =====================================================================
__global__ __launch_bounds__(256) void out_gemm(const float* __restrict__ Wo,
                                                const float* __restrict__ bo,
                                                float* __restrict__ out)
{
    extern __shared__ unsigned sm_u[];
    unsigned* Ah = sm_u;
    unsigned* Al = Ah + 4096;
    unsigned* Bh = Al + 4096;
    unsigned* Bl = Bh + 4096;

    const int m0 = blockIdx.y * 128, n0 = blockIdx.x * 128;
    const int tid = threadIdx.x, lane = tid & 31, warp = tid >> 5;
    const int wm = warp >> 2, wn = warp & 3;
    const int g = lane >> 2, t = lane & 3;
    const int am = tid >> 1;
    const int bkr = tid >> 3;

    float c[4][4][4] = {};

    for (int kk = 0; kk < DM; kk += 32) {
        if (kk) __syncthreads();
        {
            const float* ap = &g_C[(size_t)(m0 + am) * DM + kk];
            int mf = am >> 4, gg = am & 7, hm = (am >> 3) & 1;
            #pragma unroll
            for (int it = 0; it < 4; it++) {
                int k0 = (tid & 1) * 16 + it * 4;
                float4 v = *(const float4*)(ap + k0);
                int k8 = k0 >> 3, hk = (k0 >> 2) & 1, r = hm + 2 * hk;
                int base = ((mf * 4 + k8) * 32 + gg * 4) * 4 + r;
                unsigned h0 = f2tf(v.x), h1 = f2tf(v.y), h2 = f2tf(v.z), h3 = f2tf(v.w);
                Ah[base] = h0; Ah[base+4] = h1; Ah[base+8] = h2; Ah[base+12] = h3;
                Al[base]    = f2tf(v.x - __uint_as_float(h0));
                Al[base+4]  = f2tf(v.y - __uint_as_float(h1));
                Al[base+8]  = f2tf(v.z - __uint_as_float(h2));
                Al[base+12] = f2tf(v.w - __uint_as_float(h3));
            }
        }
        {
            const float* bp = &Wo[(size_t)(kk + bkr) * DM + n0];
            int tig = bkr & 3, k8 = bkr >> 3, r = (bkr >> 2) & 1;
            #pragma unroll
            for (int it = 0; it < 4; it++) {
                int ne = (tid & 7) * 16 + it * 4;
                float4 v = *(const float4*)(bp + ne);
                int nf = ne >> 3, g0 = ne & 7;
                int base = ((nf * 4 + k8) * 32 + g0 * 4 + tig) * 2 + r;
                unsigned h0 = f2tf(v.x), h1 = f2tf(v.y), h2 = f2tf(v.z), h3 = f2tf(v.w);
                Bh[base] = h0; Bh[base+8] = h1; Bh[base+16] = h2; Bh[base+24] = h3;
                Bl[base]    = f2tf(v.x - __uint_as_float(h0));
                Bl[base+8]  = f2tf(v.y - __uint_as_float(h1));
                Bl[base+16] = f2tf(v.z - __uint_as_float(h2));
                Bl[base+24] = f2tf(v.w - __uint_as_float(h3));
            }
        }
        __syncthreads();
        #pragma unroll
        for (int k8 = 0; k8 < 4; k8++) {
            unsigned ah[4][4], al[4][4], bhf[4][2], blf[4][2];
            #pragma unroll
            for (int i = 0; i < 4; i++) {
                int base = (((wm * 4 + i) * 4 + k8) * 32 + lane) * 4;
                *(uint4*)ah[i] = *(const uint4*)&Ah[base];
                *(uint4*)al[i] = *(const uint4*)&Al[base];
            }
            #pragma unroll
            for (int j = 0; j < 4; j++) {
                int base = (((wn * 4 + j) * 4 + k8) * 32 + lane) * 2;
                *(uint2*)bhf[j] = *(const uint2*)&Bh[base];
                *(uint2*)blf[j] = *(const uint2*)&Bl[base];
            }
            #pragma unroll
            for (int i = 0; i < 4; i++)
                #pragma unroll
                for (int j = 0; j < 4; j++) {
                    mma8(c[i][j], ah[i], bhf[j]);
                    mma8(c[i][j], ah[i], blf[j]);
                    mma8(c[i][j], al[i], bhf[j]);
                }
        }
    }

    #pragma unroll
    for (int i = 0; i < 4; i++) {
        #pragma unroll
        for (int j = 0; j < 4; j++) {
            int gn = n0 + wn * 32 + j * 8 + t * 2;
            float b0 = bo[gn], b1 = bo[gn + 1];
            int r0 = m0 + wm * 64 + i * 16 + g;
            *(float2*)&out[(size_t)r0 * DM + gn] =
                make_float2(c[i][j][0] + b0, c[i][j][1] + b1);
            *(float2*)&out[(size_t)(r0 + 8) * DM + gn] =
                make_float2(c[i][j][2] + b0, c[i][j][3] + b1);
        }
    }
}

// ---------------- launch ----------------
extern "C" void kernel_launch(void* const* d_in, const int* in_sizes, int n_in,
                              void* d_out, int out_size)
{
    const float* x     = (const float*)d_in[0];
    const float* delta = (const float*)d_in[1];
    const float* Wq    = (const float*)d_in[2];
    const float* bq    = (const float*)d_in[3];
    const float* Wk    = (const float*)d_in[4];
    const float* bk    = (const float*)d_in[5];
    const float* Wv    = (const float*)d_in[6];
    const float* bv    = (const float*)d_in[7];
    const float* Wo    = (const float*)d_in[8];
    const float* bo    = (const float*)d_in[9];
    float* out = (float*)d_out;
    float* outmean = out + (size_t)BB * LL * DM;

    const int QKV_SMEM = 4 * 4096 * 4;                       // 64 KB
    const int SC_SMEM  = 2 * 8192 * 4 + (128 + 1024) * 4;    // ~70 KB
    const int CTX_SMEM = (8192 + 4096) * 4 + 256 * 4;        // ~50 KB

    cudaFuncSetAttribute(qkv_gemm, cudaFuncAttributeMaxDynamicSharedMemorySize, QKV_SMEM);
    cudaFuncSetAttribute(scores_kernel, cudaFuncAttributeMaxDynamicSharedMemorySize, SC_SMEM);
    cudaFuncSetAttribute(context_kernel, cudaFuncAttributeMaxDynamicSharedMemorySize, CTX_SMEM);
    cudaFuncSetAttribute(out_gemm, cudaFuncAttributeMaxDynamicSharedMemorySize, QKV_SMEM);

    rb_kernel<<<(BB * LL + 255) / 256, 256>>>(delta);
    qkv_gemm<<<dim3(DM / 128, (BB * LL) / 128, 3), 256, QKV_SMEM>>>(x, delta, Wq, bq, Wk, bk, Wv, bv);
    scores_kernel<<<dim3(LL / 128, BH), 256, SC_SMEM>>>();
    c_kernel<<<(BH * LL + 255) / 256, 256>>>();
    context_kernel<<<dim3(LL / 128, BH), 256, CTX_SMEM>>>();
    mean_kernel<<<(unsigned)((size_t)BB * LL * LL / 4 / 256), 256>>>(outmean);
    out_gemm<<<dim3(DM / 128, (BB * LL) / 128), 256, QKV_SMEM>>>(Wo, bo, out);
}

// round 5
// speedup vs baseline: 1.1949x; 1.1949x over previous
#include <cuda_runtime.h>
#include <math.h>

#define BB 2
#define LL 2048
#define DM 1024
#define NH 16
#define DK 64
#define BH (BB*NH)

typedef unsigned long long ull;

// packed f32x2 helpers (B300 FFMA2 path)
__device__ __forceinline__ ull pk2(float x, float y) {
    ull r; asm("mov.b64 %0,{%1,%2};" : "=l"(r) : "f"(x), "f"(y)); return r;
}
__device__ __forceinline__ ull dup2(float x) { return pk2(x, x); }
__device__ __forceinline__ void fma2(ull& d, ull a, ull b) {
    asm("fma.rn.f32x2 %0,%1,%2,%0;" : "+l"(d) : "l"(a), "l"(b));
}
__device__ __forceinline__ float2 up2(ull v) {
    float2 r; asm("mov.b64 {%0,%1},%2;" : "=f"(r.x), "=f"(r.y) : "l"(v)); return r;
}

// ---------------- scratch (static __device__ allocations only) ----------------
__device__ float g_Q[(size_t)BB*NH*LL*DK];
__device__ float g_K[(size_t)BB*NH*LL*DK];
__device__ float g_V[(size_t)BB*NH*LL*DK];
__device__ float g_C[(size_t)BB*LL*DM];
__device__ float g_P[(size_t)BB*NH*LL*LL];     // raw logits
__device__ float g_m[(size_t)BB*NH*LL];
__device__ float g_s[(size_t)BB*NH*LL];
__device__ float g_c[(size_t)BB*NH*LL];
__device__ float g_rb[(size_t)BB*LL];

// ---------------- small precomputes ----------------
__global__ void rb_kernel(const float* __restrict__ delta)
{
    int i = blockIdx.x * 256 + threadIdx.x;
    if (i < BB*LL) g_rb[i] = logf(delta[i] + 1e-6f);
}
__global__ void c_kernel()
{
    int i = blockIdx.x * 256 + threadIdx.x;
    if (i < BH*LL) g_c[i] = g_m[i] + __logf(g_s[i]);
}

// ---------------- QKV projection GEMM (128x128 tile, 8x8/thread, f32x2) --------
__global__ __launch_bounds__(256) void qkv_gemm(
    const float* __restrict__ x, const float* __restrict__ delta,
    const float* __restrict__ Wq, const float* __restrict__ bq,
    const float* __restrict__ Wk, const float* __restrict__ bk,
    const float* __restrict__ Wv, const float* __restrict__ bv)
{
    const int which = blockIdx.z;
    const float* W    = (which == 0) ? Wq : (which == 1) ? Wk : Wv;
    const float* bias = (which == 0) ? bq : (which == 1) ? bk : bv;
    float* O          = (which == 0) ? g_Q : (which == 1) ? g_K : g_V;

    const int m0 = blockIdx.y * 128;
    const int n0 = blockIdx.x * 128;
    __shared__ float As[16][132];   // [k][m]
    __shared__ float Bs[16][132];   // [k][n]

    const int tid = threadIdx.x;
    const int tx = tid & 15, ty = tid >> 4;

    const int arow = tid >> 1, acol = (tid & 1) * 8;
    const int brow = tid >> 4, bcol = (tid & 15) * 8;
    const float ascale = (which == 2) ? delta[m0 + arow] : 1.0f;

    ull accp[8][4] = {};   // [i][j-pair]

    for (int kk = 0; kk < DM; kk += 16) {
        if (kk) __syncthreads();
        {   // A tile 128x16 -> transposed
            const float* ap = &x[(size_t)(m0 + arow) * DM + kk + acol];
            float4 a0 = *(const float4*)(ap);
            float4 a1 = *(const float4*)(ap + 4);
            As[acol + 0][arow] = a0.x * ascale; As[acol + 1][arow] = a0.y * ascale;
            As[acol + 2][arow] = a0.z * ascale; As[acol + 3][arow] = a0.w * ascale;
            As[acol + 4][arow] = a1.x * ascale; As[acol + 5][arow] = a1.y * ascale;
            As[acol + 6][arow] = a1.z * ascale; As[acol + 7][arow] = a1.w * ascale;
        }
        {   // B tile 16x128 -> direct
            const float* bp = &W[(size_t)(kk + brow) * DM + n0 + bcol];
            *(float4*)&Bs[brow][bcol]     = *(const float4*)(bp);
            *(float4*)&Bs[brow][bcol + 4] = *(const float4*)(bp + 4);
        }
        __syncthreads();
        #pragma unroll
        for (int k = 0; k < 16; k++) {
            float4 a0 = *(const float4*)&As[k][ty * 4];
            float4 a1 = *(const float4*)&As[k][64 + ty * 4];
            longlong2 bq0 = *(const longlong2*)&Bs[k][tx * 4];
            longlong2 bq1 = *(const longlong2*)&Bs[k][64 + tx * 4];
            ull bb[4] = {(ull)bq0.x, (ull)bq0.y, (ull)bq1.x, (ull)bq1.y};
            ull ad[8] = {dup2(a0.x), dup2(a0.y), dup2(a0.z), dup2(a0.w),
                         dup2(a1.x), dup2(a1.y), dup2(a1.z), dup2(a1.w)};
            #pragma unroll
            for (int i = 0; i < 8; i++)
                #pragma unroll
                for (int jp = 0; jp < 4; jp++)
                    fma2(accp[i][jp], ad[i], bb[jp]);
        }
    }

    #pragma unroll
    for (int i = 0; i < 8; i++) {
        int gm = m0 + (i >> 2) * 64 + ty * 4 + (i & 3);
        int b = gm >> 11, l = gm & (LL - 1);
        #pragma unroll
        for (int gj = 0; gj < 2; gj++) {
            int gn = n0 + gj * 64 + tx * 4;
            int h = gn >> 6, d = gn & 63;
            float2 p0 = up2(accp[i][gj * 2 + 0]);
            float2 p1 = up2(accp[i][gj * 2 + 1]);
            float4 v = make_float4(p0.x + bias[gn+0], p0.y + bias[gn+1],
                                   p1.x + bias[gn+2], p1.y + bias[gn+3]);
            *(float4*)&O[(((size_t)(b * NH + h)) * LL + l) * DK + d] = v;
        }
    }
}

// ---------------- scores (128q x 128k tile, 8x8/thread, f32x2) + online stats ---
__global__ __launch_bounds__(256) void scores_kernel()
{
    const int bh = blockIdx.y;
    const int b  = bh >> 4;
    const int q0 = blockIdx.x * 128;

    __shared__ float Qs[32][132];   // [d][q]
    __shared__ float Ks[32][132];   // [d][k]

    const int tid = threadIdx.x;
    const int tx = tid & 15, ty = tid >> 4;
    const int lrow = tid >> 1, lcolh = (tid & 1) * 16;

    const float* Qbase = g_Q + (((size_t)bh) * LL + q0 + lrow) * DK + lcolh;

    float mreg[8], sreg[8];
    #pragma unroll
    for (int i = 0; i < 8; i++) { mreg[i] = -1e30f; sreg[i] = 0.0f; }

    for (int kt = 0; kt < LL / 128; kt++) {
        ull accp[8][4] = {};
        const float* Kbase = g_K + (((size_t)bh) * LL + kt * 128 + lrow) * DK + lcolh;

        #pragma unroll
        for (int dc = 0; dc < 64; dc += 32) {
            __syncthreads();
            #pragma unroll
            for (int it = 0; it < 4; it++) {
                float4 qv = *(const float4*)(Qbase + dc + it * 4);
                int d = lcolh + it * 4;
                Qs[d + 0][lrow] = qv.x; Qs[d + 1][lrow] = qv.y;
                Qs[d + 2][lrow] = qv.z; Qs[d + 3][lrow] = qv.w;
                float4 kv = *(const float4*)(Kbase + dc + it * 4);
                Ks[d + 0][lrow] = kv.x; Ks[d + 1][lrow] = kv.y;
                Ks[d + 2][lrow] = kv.z; Ks[d + 3][lrow] = kv.w;
            }
            __syncthreads();
            #pragma unroll
            for (int d = 0; d < 32; d++) {
                float4 a0 = *(const float4*)&Qs[d][ty * 4];
                float4 a1 = *(const float4*)&Qs[d][64 + ty * 4];
                longlong2 bq0 = *(const longlong2*)&Ks[d][tx * 4];
                longlong2 bq1 = *(const longlong2*)&Ks[d][64 + tx * 4];
                ull bb[4] = {(ull)bq0.x, (ull)bq0.y, (ull)bq1.x, (ull)bq1.y};
                ull ad[8] = {dup2(a0.x), dup2(a0.y), dup2(a0.z), dup2(a0.w),
                             dup2(a1.x), dup2(a1.y), dup2(a1.z), dup2(a1.w)};
                #pragma unroll
                for (int i = 0; i < 8; i++)
                    #pragma unroll
                    for (int jp = 0; jp < 4; jp++)
                        fma2(accp[i][jp], ad[i], bb[jp]);
            }
        }

        // bias + logits store + online stats
        float rb8[8];
        #pragma unroll
        for (int j = 0; j < 8; j++)
            rb8[j] = g_rb[(size_t)b * LL + kt * 128 + (j >> 2) * 64 + tx * 4 + (j & 3)];

        #pragma unroll
        for (int i = 0; i < 8; i++) {
            int qg = q0 + (i >> 2) * 64 + ty * 4 + (i & 3);
            float sv[8];
            #pragma unroll
            for (int jp = 0; jp < 4; jp++) {
                float2 p = up2(accp[i][jp]);
                sv[jp * 2 + 0] = p.x;
                sv[jp * 2 + 1] = p.y;
            }
            #pragma unroll
            for (int j = 0; j < 8; j++) {
                int kg = kt * 128 + (j >> 2) * 64 + tx * 4 + (j & 3);
                sv[j] = sv[j] * 0.125f - 0.1f * fabsf((float)(qg - kg)) + rb8[j];
            }
            float* prow = &g_P[(((size_t)bh) * LL + qg) * LL + kt * 128];
            __stcs((float4*)&prow[tx * 4],      make_float4(sv[0], sv[1], sv[2], sv[3]));
            __stcs((float4*)&prow[64 + tx * 4], make_float4(sv[4], sv[5], sv[6], sv[7]));

            float tm = sv[0];
            #pragma unroll
            for (int j = 1; j < 8; j++) tm = fmaxf(tm, sv[j]);
            #pragma unroll
            for (int o = 8; o >= 1; o >>= 1)
                tm = fmaxf(tm, __shfl_xor_sync(0xffffffffu, tm, o, 16));
            float newm = fmaxf(mreg[i], tm);
            float ls = 0.0f;
            #pragma unroll
            for (int j = 0; j < 8; j++) ls += __expf(sv[j] - newm);
            #pragma unroll
            for (int o = 8; o >= 1; o >>= 1)
                ls += __shfl_xor_sync(0xffffffffu, ls, o, 16);
            sreg[i] = sreg[i] * __expf(mreg[i] - newm) + ls;
            mreg[i] = newm;
        }
    }

    if (tx == 0) {
        #pragma unroll
        for (int i = 0; i < 8; i++) {
            int qg = q0 + (i >> 2) * 64 + ty * 4 + (i & 3);
            size_t ridx = (size_t)bh * LL + qg;
            g_m[ridx] = mreg[i];
            g_s[ridx] = sreg[i];
        }
    }
}

// ---------------- context = softmax(P) @ V  (128q x 64d, 8x4/thread, f32x2) -----
__global__ __launch_bounds__(256) void context_kernel()
{
    const int bh = blockIdx.y;
    const int b = bh >> 4, h = bh & 15;
    const int q0 = blockIdx.x * 128;

    __shared__ float Ps[32][132];   // [key][q], exp(l - m)
    __shared__ float Vs[32][68];    // [key][d]
    __shared__ float mrow[128], irow[128];

    const int tid = threadIdx.x;
    const int tx = tid & 15, ty = tid >> 4;

    if (tid < 128) {
        size_t ridx = (size_t)bh * LL + q0 + tid;
        mrow[tid] = g_m[ridx];
        irow[tid] = 1.0f / g_s[ridx];
    }

    const int prow = tid >> 1, pk = (tid & 1) * 16;
    const int vrow = tid >> 3, vcol = (tid & 7) * 8;

    const float* Pbase = g_P + (((size_t)bh) * LL + q0 + prow) * LL + pk;

    ull accp[4][4] = {};   // [i-pair][j]

    for (int kc = 0; kc < LL; kc += 32) {
        __syncthreads();
        {
            float pm = mrow[prow];
            #pragma unroll
            for (int it = 0; it < 4; it++) {
                float4 v = __ldcs((const float4*)(Pbase + kc + it * 4));
                int k = pk + it * 4;
                Ps[k + 0][prow] = __expf(v.x - pm);
                Ps[k + 1][prow] = __expf(v.y - pm);
                Ps[k + 2][prow] = __expf(v.z - pm);
                Ps[k + 3][prow] = __expf(v.w - pm);
            }
            const float* vp = &g_V[(((size_t)bh) * LL + kc + vrow) * DK + vcol];
            *(float4*)&Vs[vrow][vcol]     = *(const float4*)(vp);
            *(float4*)&Vs[vrow][vcol + 4] = *(const float4*)(vp + 4);
        }
        __syncthreads();
        #pragma unroll
        for (int k = 0; k < 32; k++) {
            longlong2 aq0 = *(const longlong2*)&Ps[k][ty * 4];
            longlong2 aq1 = *(const longlong2*)&Ps[k][64 + ty * 4];
            ull aa[4] = {(ull)aq0.x, (ull)aq0.y, (ull)aq1.x, (ull)aq1.y};
            float4 bv4 = *(const float4*)&Vs[k][tx * 4];
            ull bd[4] = {dup2(bv4.x), dup2(bv4.y), dup2(bv4.z), dup2(bv4.w)};
            #pragma unroll
            for (int ip = 0; ip < 4; ip++)
                #pragma unroll
                for (int j = 0; j < 4; j++)
                    fma2(accp[ip][j], aa[ip], bd[j]);
        }
    }

    #pragma unroll
    for (int ip = 0; ip < 4; ip++) {
        // pair (2ip, 2ip+1) within 8 i-rows; both stay in same 64-group
        float2 r0 = up2(accp[ip][0]);
        float2 r1 = up2(accp[ip][1]);
        float2 r2 = up2(accp[ip][2]);
        float2 r3 = up2(accp[ip][3]);
        int i0 = 2 * ip, i1 = 2 * ip + 1;
        int lq0 = (i0 >> 2) * 64 + ty * 4 + (i0 & 3);
        int lq1 = (i1 >> 2) * 64 + ty * 4 + (i1 & 3);
        float s0 = irow[lq0], s1 = irow[lq1];
        *(float4*)&g_C[((size_t)(b * LL + q0 + lq0)) * DM + h * 64 + tx * 4] =
            make_float4(r0.x * s0, r1.x * s0, r2.x * s0, r3.x * s0);
        *(float4*)&g_C[((size_t)(b * LL + q0 + lq1)) * DM + h * 64 + tx * 4] =
            make_float4(r0.y * s1, r1.y * s1, r2.y * s1, r3.y * s1);
    }
}

// ---------------- head-mean of attention (4 k per thread) ----------------
__global__ void mean_kernel(float* __restrict__ outmean)
{
    size_t idx4 = (size_t)blockIdx.x * 256 + threadIdx.x;
    int k4 = (int)(idx4 & (LL / 4 - 1)) * 4;
    size_t bq = idx4 / (LL / 4);
    int q = (int)(bq & (LL - 1));
    int b = (int)(bq >> 11);
    float ax = 0, ay = 0, az = 0, aw = 0;
    #pragma unroll
    for (int h = 0; h < NH; h++) {
        int bh = b * NH + h;
        float c = g_c[(size_t)bh * LL + q];
        float4 v = __ldcs((const float4*)&g_P[((size_t)bh * LL + q) * LL + k4]);
        ax += __expf(v.x - c); ay += __expf(v.y - c);
        az += __expf(v.z - c); aw += __expf(v.w - c);
    }
    const float inv = 1.0f / NH;
    *(float4*)&outmean[bq * LL + k4] =
        make_float4(ax * inv, ay * inv, az * inv, aw * inv);
}

// ---------------- output projection (128x128 tile, 8x8/thread, f32x2) -----------
__global__ __launch_bounds__(256) void out_gemm(const float* __restrict__ Wo,
                                                const float* __restrict__ bo,
                                                float* __restrict__ out)
{
    const int m0 = blockIdx.y * 128;
    const int n0 = blockIdx.x * 128;
    __shared__ float As[16][132];
    __shared__ float Bs[16][132];

    const int tid = threadIdx.x;
    const int tx = tid & 15, ty = tid >> 4;
    const int arow = tid >> 1, acol = (tid & 1) * 8;
    const int brow = tid >> 4, bcol = (tid & 15) * 8;

    ull accp[8][4] = {};

    for (int kk = 0; kk < DM; kk += 16) {
        if (kk) __syncthreads();
        {
            const float* ap = &g_C[(size_t)(m0 + arow) * DM + kk + acol];
            float4 a0 = *(const float4*)(ap);
            float4 a1 = *(const float4*)(ap + 4);
            As[acol + 0][arow] = a0.x; As[acol + 1][arow] = a0.y;
            As[acol + 2][arow] = a0.z; As[acol + 3][arow] = a0.w;
            As[acol + 4][arow] = a1.x; As[acol + 5][arow] = a1.y;
            As[acol + 6][arow] = a1.z; As[acol + 7][arow] = a1.w;
        }
        {
            const float* bp = &Wo[(size_t)(kk + brow) * DM + n0 + bcol];
            *(float4*)&Bs[brow][bcol]     = *(const float4*)(bp);
            *(float4*)&Bs[brow][bcol + 4] = *(const float4*)(bp + 4);
        }
        __syncthreads();
        #pragma unroll
        for (int k = 0; k < 16; k++) {
            float4 a0 = *(const float4*)&As[k][ty * 4];
            float4 a1 = *(const float4*)&As[k][64 + ty * 4];
            longlong2 bq0 = *(const longlong2*)&Bs[k][tx * 4];
            longlong2 bq1 = *(const longlong2*)&Bs[k][64 + tx * 4];
            ull bb[4] = {(ull)bq0.x, (ull)bq0.y, (ull)bq1.x, (ull)bq1.y};
            ull ad[8] = {dup2(a0.x), dup2(a0.y), dup2(a0.z), dup2(a0.w),
                         dup2(a1.x), dup2(a1.y), dup2(a1.z), dup2(a1.w)};
            #pragma unroll
            for (int i = 0; i < 8; i++)
                #pragma unroll
                for (int jp = 0; jp < 4; jp++)
                    fma2(accp[i][jp], ad[i], bb[jp]);
        }
    }

    #pragma unroll
    for (int i = 0; i < 8; i++) {
        int gm = m0 + (i >> 2) * 64 + ty * 4 + (i & 3);
        #pragma unroll
        for (int gj = 0; gj < 2; gj++) {
            int gn = n0 + gj * 64 + tx * 4;
            float2 p0 = up2(accp[i][gj * 2 + 0]);
            float2 p1 = up2(accp[i][gj * 2 + 1]);
            float4 v = make_float4(p0.x + bo[gn+0], p0.y + bo[gn+1],
                                   p1.x + bo[gn+2], p1.y + bo[gn+3]);
            *(float4*)&out[(size_t)gm * DM + gn] = v;
        }
    }
}

// ---------------- launch ----------------
extern "C" void kernel_launch(void* const* d_in, const int* in_sizes, int n_in,
                              void* d_out, int out_size)
{
    const float* x     = (const float*)d_in[0];
    const float* delta = (const float*)d_in[1];
    const float* Wq    = (const float*)d_in[2];
    const float* bq    = (const float*)d_in[3];
    const float* Wk    = (const float*)d_in[4];
    const float* bk    = (const float*)d_in[5];
    const float* Wv    = (const float*)d_in[6];
    const float* bv    = (const float*)d_in[7];
    const float* Wo    = (const float*)d_in[8];
    const float* bo    = (const float*)d_in[9];
    float* out = (float*)d_out;
    float* outmean = out + (size_t)BB * LL * DM;

    rb_kernel<<<(BB * LL + 255) / 256, 256>>>(delta);
    qkv_gemm<<<dim3(DM / 128, (BB * LL) / 128, 3), 256>>>(x, delta, Wq, bq, Wk, bk, Wv, bv);
    scores_kernel<<<dim3(LL / 128, BH), 256>>>();
    c_kernel<<<(BH * LL + 255) / 256, 256>>>();
    context_kernel<<<dim3(LL / 128, BH), 256>>>();
    mean_kernel<<<(unsigned)((size_t)BB * LL * LL / 4 / 256), 256>>>(outmean);
    out_gemm<<<dim3(DM / 128, (BB * LL) / 128), 256>>>(Wo, bo, out);
}